// round 15
// baseline (speedup 1.0000x reference)
#include <cuda_runtime.h>
#include <cuda_bf16.h>
#include <math.h>
#include <stdint.h>

// B=8, N=64, D=64, E=32. GEMM view: (32768 x 32) @ (32 x 4096), fused
// relu/mask/reduce epilogue + GRU tail. Single-pass TF32 mma.sync m16n8k8.
// R15: two m-tiles per step -> 4 independent MMA chains per nt (8 MMAs in
// flight before any result is consumed), B hoisted 4-nt to keep live regs
// ~111 (< 128, no spill).

typedef unsigned int u32;

// W fragment buffer: [ig(64)][nt(8)][half(2)][lane(32)] uint4
//   half 0 = ktiles 0,1 ; half 1 = ktiles 2,3
__device__ uint4 g_Wfrag4[32768];   // 512 KB

static __device__ __forceinline__ u32 tf32cvt(float v) {
    u32 r;
    asm("cvt.rna.tf32.f32 %0, %1;" : "=r"(r) : "f"(v));
    return r;
}

#define MMAT32(c0,c1,c2,c3,a0,a1,a2,a3,b0,b1) \
    asm volatile("mma.sync.aligned.m16n8k8.row.col.f32.tf32.tf32.f32 " \
        "{%0,%1,%2,%3},{%4,%5,%6,%7},{%8,%9},{%0,%1,%2,%3};" \
        : "+f"(c0),"+f"(c1),"+f"(c2),"+f"(c3) \
        : "r"(a0),"r"(a1),"r"(a2),"r"(a3),"r"(b0),"r"(b1))

// ---------------- converter: W_e -> tf32 fragments ----------------
__global__ void conv_w_kernel(const float* __restrict__ W_e) {
    int idx  = blockIdx.x * 256 + threadIdx.x;   // 0..32767, one uint4 each
    int lane = idx & 31;
    int half = (idx >> 5) & 1;
    int ntig = idx >> 6;                          // ig*8 + nt
    int ncol = (ntig << 3) + (lane >> 2);
    int k0   = half * 16 + (lane & 3);
    uint4 v;
    v.x = tf32cvt(W_e[(size_t)k0 * 4096 + ncol]);
    v.y = tf32cvt(W_e[(size_t)(k0 + 4) * 4096 + ncol]);
    v.z = tf32cvt(W_e[(size_t)(k0 + 8) * 4096 + ncol]);
    v.w = tf32cvt(W_e[(size_t)(k0 + 12) * 4096 + ncol]);
    g_Wfrag4[idx] = v;
}

// ---------------- main kernel ----------------
// dynamic smem layout (bytes)
#define OFF_AF    0        // A frags: [mt(8)][kt(4)][lane(32)] uint4 = 16KB
#define OFF_WF    16384    // wt frags: [mt(8)][nt(8)][lane(32)] float4 = 32KB
#define OFF_AGGS  49152    // 128 f
#define OFF_XROW  49664    // 128 f
#define OFF_XK1   50176    // 192 f
#define OFF_H1    50944    // 64 f
#define OFF_XK2   51200    // 192 f
#define OFF_HK2   51968    // 192 f
#define SMEM_SZ   52736

__global__ __launch_bounds__(256, 2) void mp_mma_kernel(
    const float* __restrict__ nodes,   // (8,64,64)
    const float* __restrict__ edges,   // (8,4096,32)
    const float* __restrict__ mask,    // (8,4096,1)
    const float* __restrict__ b_e,     // (4096,)
    const float* __restrict__ Kmat,    // (64,192)
    const float* __restrict__ Rmat,    // (64,192)
    const float* __restrict__ gbias,   // (2,192)
    float* __restrict__ out)           // (8,64,64)
{
    extern __shared__ char sm[];
    u32*    AF   = (u32*)(sm + OFF_AF);
    uint4*  AF4  = (uint4*)(sm + OFF_AF);
    float4* WF4  = (float4*)(sm + OFF_WF);
    float*  aggs = (float*)(sm + OFF_AGGS);
    float*  xrow = (float*)(sm + OFF_XROW);
    float*  xk1  = (float*)(sm + OFF_XK1);
    float*  h1   = (float*)(sm + OFF_H1);
    float*  xk2  = (float*)(sm + OFF_XK2);
    float*  hk2  = (float*)(sm + OFF_HK2);

    const int t    = threadIdx.x;
    const int lane = t & 31;
    const int wid  = t >> 5;          // 0..7
    const int b    = blockIdx.x >> 5;
    const int pair = blockIdx.x & 31;

    if (t < 128)
        xrow[t] = nodes[((size_t)b * 64 + pair * 2 + (t >> 6)) * 64 + (t & 63)];

    // ---- A staging: edges rows -> tf32 fragment-major smem ----
    {
        int m = t >> 1, half = t & 1;
        int mt = m >> 4, r16 = m & 15;
        const float* ar = edges + ((size_t)(b * 4096 + pair * 128 + m)) * 32 + half * 16;
        float v[16];
        #pragma unroll
        for (int i = 0; i < 16; i += 4) {
            float4 x = *(const float4*)(ar + i);
            v[i] = x.x; v[i + 1] = x.y; v[i + 2] = x.z; v[i + 3] = x.w;
        }
        #pragma unroll
        for (int i = 0; i < 16; i++) {
            int k   = half * 16 + i;
            int kt  = k >> 3;
            int reg = (r16 >> 3) + 2 * ((k >> 2) & 1);
            int ln  = (r16 & 7) * 4 + (k & 3);
            AF[((mt * 4 + kt) * 32 + ln) * 4 + reg] = tf32cvt(v[i]);
        }
    }
    // ---- wt fragments: mask*nodes in fragment-major float4 ----
    for (int idx = t; idx < 2048; idx += 256) {
        int mt = idx >> 8, nt = (idx >> 5) & 7, ln = idx & 31;
        int rr = ln >> 2, q = ln & 3;
        int mrow = mt * 16 + rr;
        int c = nt * 8 + 2 * q;
        int il = mrow >> 6;
        int jn1 = mrow & 63, jn2 = (mrow + 8) & 63;
        float m1 = mask[(size_t)b * 4096 + (pair * 2 + il) * 64 + jn1];
        float m2 = mask[(size_t)b * 4096 + (pair * 2 + il) * 64 + jn2];
        float2 n1 = *(const float2*)(nodes + ((size_t)b * 64 + jn1) * 64 + c);
        float2 n2 = *(const float2*)(nodes + ((size_t)b * 64 + jn2) * 64 + c);
        float4 w; w.x = n1.x * m1; w.y = n1.y * m1; w.z = n2.x * m2; w.w = n2.y * m2;
        WF4[idx] = w;
    }
    __syncthreads();

    const int q = lane & 3;

    for (int igl = 0; igl < 8; igl++) {
        const int ig = wid * 8 + igl;
        float s0 = 0.f, s1 = 0.f;

        #pragma unroll
        for (int nh = 0; nh < 2; nh++) {
            // B fragments for 4 nt (32 regs) + bias (8 regs)
            uint4 Bh[4], Bl[4];
            float2 bb[4];
            #pragma unroll
            for (int j = 0; j < 4; j++) {
                int nt = nh * 4 + j;
                Bh[j] = g_Wfrag4[((ig * 8 + nt) * 2 + 0) * 32 + lane];
                Bl[j] = g_Wfrag4[((ig * 8 + nt) * 2 + 1) * 32 + lane];
                bb[j] = __ldg((const float2*)(b_e + ig * 64 + nt * 8 + 2 * q));
            }

            #pragma unroll
            for (int mtp = 0; mtp < 4; mtp++) {
                const int mt0 = mtp * 2, mt1 = mt0 + 1;
                uint4 A00 = AF4[(mt0 * 4 + 0) * 32 + lane];
                uint4 A01 = AF4[(mt0 * 4 + 1) * 32 + lane];
                uint4 A02 = AF4[(mt0 * 4 + 2) * 32 + lane];
                uint4 A03 = AF4[(mt0 * 4 + 3) * 32 + lane];
                uint4 A10 = AF4[(mt1 * 4 + 0) * 32 + lane];
                uint4 A11 = AF4[(mt1 * 4 + 1) * 32 + lane];
                uint4 A12 = AF4[(mt1 * 4 + 2) * 32 + lane];
                uint4 A13 = AF4[(mt1 * 4 + 3) * 32 + lane];

                float sm0 = 0.f, sm1 = 0.f;
                #pragma unroll
                for (int j = 0; j < 4; j++) {
                    int nt = nh * 4 + j;
                    // 4 independent chains: (c,d) per mt
                    float c00 = bb[j].x, c01 = bb[j].y, c02 = bb[j].x, c03 = bb[j].y;
                    float d00 = 0.f, d01 = 0.f, d02 = 0.f, d03 = 0.f;
                    float c10 = bb[j].x, c11 = bb[j].y, c12 = bb[j].x, c13 = bb[j].y;
                    float d10 = 0.f, d11 = 0.f, d12 = 0.f, d13 = 0.f;

                    MMAT32(c00,c01,c02,c03, A00.x,A00.y,A00.z,A00.w, Bh[j].x, Bh[j].y);
                    MMAT32(c10,c11,c12,c13, A10.x,A10.y,A10.z,A10.w, Bh[j].x, Bh[j].y);
                    MMAT32(d00,d01,d02,d03, A02.x,A02.y,A02.z,A02.w, Bl[j].x, Bl[j].y);
                    MMAT32(d10,d11,d12,d13, A12.x,A12.y,A12.z,A12.w, Bl[j].x, Bl[j].y);
                    MMAT32(c00,c01,c02,c03, A01.x,A01.y,A01.z,A01.w, Bh[j].z, Bh[j].w);
                    MMAT32(c10,c11,c12,c13, A11.x,A11.y,A11.z,A11.w, Bh[j].z, Bh[j].w);
                    MMAT32(d00,d01,d02,d03, A03.x,A03.y,A03.z,A03.w, Bl[j].z, Bl[j].w);
                    MMAT32(d10,d11,d12,d13, A13.x,A13.y,A13.z,A13.w, Bl[j].z, Bl[j].w);

                    float4 w0 = WF4[(mt0 * 8 + nt) * 32 + lane];
                    float4 w1 = WF4[(mt1 * 8 + nt) * 32 + lane];
                    sm0 = fmaf(fmaxf(c00 + d00, 0.0f), w0.x, sm0);
                    sm0 = fmaf(fmaxf(c01 + d01, 0.0f), w0.y, sm0);
                    sm0 = fmaf(fmaxf(c02 + d02, 0.0f), w0.z, sm0);
                    sm0 = fmaf(fmaxf(c03 + d03, 0.0f), w0.w, sm0);
                    sm1 = fmaf(fmaxf(c10 + d10, 0.0f), w1.x, sm1);
                    sm1 = fmaf(fmaxf(c11 + d11, 0.0f), w1.y, sm1);
                    sm1 = fmaf(fmaxf(c12 + d12, 0.0f), w1.z, sm1);
                    sm1 = fmaf(fmaxf(c13 + d13, 0.0f), w1.w, sm1);
                }
                if (mtp < 2) s0 += sm0 + sm1; else s1 += sm0 + sm1;
            }
        }
        // warp reduce; single writer per agg cell -> plain stores
        #pragma unroll
        for (int off = 16; off; off >>= 1) {
            s0 += __shfl_down_sync(0xffffffffu, s0, off);
            s1 += __shfl_down_sync(0xffffffffu, s1, off);
        }
        if (lane == 0) {
            aggs[ig]      = s0;
            aggs[64 + ig] = s1;
        }
    }
    __syncthreads();

    // ---- GRU tail: 2 inodes ----
    for (int il2 = 0; il2 < 2; il2++) {
        __syncthreads();
        if (t < 192) {
            float s = gbias[t];
            #pragma unroll 8
            for (int k = 0; k < 64; k++)
                s = fmaf(xrow[il2 * 64 + k], Kmat[k * 192 + t], s);
            xk1[t] = s;
        }
        __syncthreads();
        if (t < 64) {
            float z  = 1.0f / (1.0f + expf(-(xk1[t] + gbias[192 + t])));
            float r  = 1.0f / (1.0f + expf(-(xk1[64 + t] + gbias[256 + t])));
            float hh = tanhf(xk1[128 + t] + r * gbias[320 + t]);
            h1[t] = (1.0f - z) * hh;   // h was 0
        }
        __syncthreads();
        if (t < 192) {
            float s1g = gbias[t], s2g = gbias[192 + t];
            #pragma unroll 8
            for (int k = 0; k < 64; k++) {
                s1g = fmaf(aggs[il2 * 64 + k], Kmat[k * 192 + t], s1g);
                s2g = fmaf(h1[k],              Rmat[k * 192 + t], s2g);
            }
            xk2[t] = s1g; hk2[t] = s2g;
        }
        __syncthreads();
        if (t < 64) {
            float z  = 1.0f / (1.0f + expf(-(xk2[t] + hk2[t])));
            float r  = 1.0f / (1.0f + expf(-(xk2[64 + t] + hk2[64 + t])));
            float hh = tanhf(xk2[128 + t] + r * hk2[128 + t]);
            out[((size_t)(b * 64 + pair * 2 + il2)) * 64 + t] =
                z * h1[t] + (1.0f - z) * hh;
        }
    }
}

extern "C" void kernel_launch(void* const* d_in, const int* in_sizes, int n_in,
                              void* d_out, int out_size) {
    const float* nodes = (const float*)d_in[0];
    const float* edges = (const float*)d_in[1];
    const float* mask  = (const float*)d_in[2];
    const float* W_e   = (const float*)d_in[3];
    const float* b_e   = (const float*)d_in[4];
    const float* gk    = (const float*)d_in[5];
    const float* gr    = (const float*)d_in[6];
    const float* gb    = (const float*)d_in[7];
    float* out = (float*)d_out;

    conv_w_kernel<<<128, 256>>>(W_e);

    cudaFuncSetAttribute(mp_mma_kernel,
                         cudaFuncAttributeMaxDynamicSharedMemorySize, SMEM_SZ);
    mp_mma_kernel<<<256, 256, SMEM_SZ>>>(nodes, edges, mask, b_e,
                                         gk, gr, gb, out);
}